// round 2
// baseline (speedup 1.0000x reference)
#include <cuda_runtime.h>

// ConvQuadInterp3d over x:(2,1,8,512,512) fp32.
// Output = coords_max (B,1,3,D,H,W) then y_max (B,1,D,H,W), fp32.
// Each thread handles 4 consecutive w (float4 I/O), rolling 3-plane register window.

#define Dd 8
#define Hh 512
#define Ww 512
#define Bb 2
#define PLANE (Hh * Ww)

// Load 6 consecutive values covering [w0-1, w0+4] with replicate clamp.
__device__ __forceinline__ void load_row6(const float* __restrict__ row, int w0, float* v) {
    const float4 q = *reinterpret_cast<const float4*>(row + w0);
    v[1] = q.x; v[2] = q.y; v[3] = q.z; v[4] = q.w;
    v[0] = (w0 == 0)      ? q.x : __ldg(row + w0 - 1);
    v[5] = (w0 == Ww - 4) ? q.w : __ldg(row + w0 + 4);
}

__device__ __forceinline__ void load_plane18(const float* __restrict__ x, int base,
                                             int hm, int h0, int hp, int w0, float* p) {
    load_row6(x + base + hm * Ww, w0, p + 0);   // row h-1
    load_row6(x + base + h0 * Ww, w0, p + 6);   // row h
    load_row6(x + base + hp * Ww, w0, p + 12);  // row h+1
}

__global__ void __launch_bounds__(256)
conv_quad_interp3d_kernel(const float* __restrict__ x, float* __restrict__ out) {
    const int w0 = (blockIdx.x * 64 + threadIdx.x) * 4;  // 0..508, multiple of 4
    const int h  = blockIdx.y * 4 + threadIdx.y;
    const int b  = blockIdx.z;

    const int hm = max(h - 1, 0), hp = min(h + 1, Hh - 1);
    const int xbase = b * Dd * PLANE;

    // Rolling register window: P0 = plane d-1, P1 = d, P2 = d+1 (clamped).
    // Layout: [row * 6 + (w - (w0-1))], rows = {h-1, h, h+1}.
    float P0[18], P1[18], P2[18];
    load_plane18(x, xbase + 0 * PLANE, hm, h, hp, w0, P1);
#pragma unroll
    for (int i = 0; i < 18; i++) P0[i] = P1[i];           // replicate pad d = -1
    load_plane18(x, xbase + 1 * PLANE, hm, h, hp, w0, P2);

    const int hw = h * Ww + w0;
    float* coordsD = out + (b * 3 + 0) * Dd * PLANE;
    float* coordsW = out + (b * 3 + 1) * Dd * PLANE;
    float* coordsH = out + (b * 3 + 2) * Dd * PLANE;
    float* ymax    = out + (Bb * 3) * Dd * PLANE + b * Dd * PLANE;

#pragma unroll 1
    for (int d = 0; d < Dd; d++) {
        float rD[4], rW[4], rH[4], rY[4];

#pragma unroll
        for (int wi = 0; wi < 4; wi++) {
            const int j = wi;  // left index within 6-wide rows
            const float c = P1[6 + j + 1];

            // Gradient (central diff / 2, replicate pad)
            const float gx = 0.5f * (P1[6 + j + 2] - P1[6 + j]);
            const float gy = 0.5f * (P1[12 + j + 1] - P1[j + 1]);
            const float gs = 0.5f * (P2[6 + j + 1] - P0[6 + j + 1]);

            // Hessian (cross terms * 0.25 per reference)
            const float axx = P1[6 + j] + P1[6 + j + 2] - 2.0f * c;
            const float ayy = P1[j + 1] + P1[12 + j + 1] - 2.0f * c;
            const float ass = P0[6 + j + 1] + P2[6 + j + 1] - 2.0f * c;
            const float axy = 0.25f * (P1[j] + P1[12 + j + 2] - P1[12 + j] - P1[j + 2]);
            const float ays = 0.25f * (P0[j + 1] + P2[12 + j + 1] - P2[j + 1] - P0[12 + j + 1]);
            const float axs = 0.25f * (P0[6 + j] + P2[6 + j + 2] - P2[6 + j] - P0[6 + j + 2]);

            // NMS over 3x3x3 neighborhood (clamped == -inf-pad maxpool)
            float m = c;
#pragma unroll
            for (int r = 0; r < 3; r++) {
#pragma unroll
                for (int q = 0; q < 3; q++) {
                    m = fmaxf(m, P0[r * 6 + j + q]);
                    m = fmaxf(m, P1[r * 6 + j + q]);
                    m = fmaxf(m, P2[r * 6 + j + q]);
                }
            }
            const bool nms = (c == m);

            // Symmetric 3x3 solve via adjugate
            const float c00 = ayy * ass - ays * ays;
            const float c01 = axs * ays - axy * ass;
            const float c02 = axy * ays - axs * ayy;
            const float det = axx * c00 + axy * c01 + axs * c02;
            const bool keep = nms && (det != 0.0f);

            float rx = 0.0f, ry = 0.0f, rs = 0.0f;
            if (keep) {
                const float inv = 1.0f / det;
                const float c11 = axx * ass - axs * axs;
                const float c12 = axy * axs - axx * ays;
                const float c22 = axx * ayy - axy * axy;
                rx = -(c00 * gx + c01 * gy + c02 * gs) * inv;
                ry = -(c01 * gx + c11 * gy + c12 * gs) * inv;
                rs = -(c02 * gx + c12 * gy + c22 * gs) * inv;
                const float big = fmaxf(fabsf(rx), fmaxf(fabsf(ry), fabsf(rs)));
                if (big > 0.7f) { rx = 0.0f; ry = 0.0f; rs = 0.0f; }
            }

            const float dyv = 0.5f * (gx * rx + gy * ry + gs * rs);
            rY[wi] = c + dyv + (keep ? 10.0f : 0.0f);
            // grid channels (d, w, h) + flipped refinement (s, y, x)
            rD[wi] = (float)d + rs;
            rW[wi] = (float)(w0 + wi) + ry;
            rH[wi] = (float)h + rx;
        }

        const int dhw = d * PLANE + hw;
        *reinterpret_cast<float4*>(coordsD + dhw) = make_float4(rD[0], rD[1], rD[2], rD[3]);
        *reinterpret_cast<float4*>(coordsW + dhw) = make_float4(rW[0], rW[1], rW[2], rW[3]);
        *reinterpret_cast<float4*>(coordsH + dhw) = make_float4(rH[0], rH[1], rH[2], rH[3]);
        *reinterpret_cast<float4*>(ymax    + dhw) = make_float4(rY[0], rY[1], rY[2], rY[3]);

        if (d < Dd - 1) {
#pragma unroll
            for (int i = 0; i < 18; i++) { P0[i] = P1[i]; P1[i] = P2[i]; }
            const int dn = min(d + 2, Dd - 1);
            load_plane18(x, xbase + dn * PLANE, hm, h, hp, w0, P2);
        }
    }
}

extern "C" void kernel_launch(void* const* d_in, const int* in_sizes, int n_in,
                              void* d_out, int out_size) {
    const float* x = (const float*)d_in[0];
    float* out = (float*)d_out;
    dim3 block(64, 4, 1);                 // 64 w-threads (x4 wide) x 4 h
    dim3 grid(Ww / (64 * 4), Hh / 4, Bb); // (2, 128, 2)
    conv_quad_interp3d_kernel<<<grid, block>>>(x, out);
}

// round 3
// speedup vs baseline: 1.6852x; 1.6852x over previous
#include <cuda_runtime.h>

// ConvQuadInterp3d over x:(2,1,8,512,512) fp32.
// Output = coords_max (B,1,3,D,H,W) then y_max (B,1,D,H,W), fp32.
// One thread per (b,h,w); fully-unrolled d loop with rolling 3-plane 3x3 register
// window + cached per-plane column maxima for separable NMS.

#define Dd 8
#define Hh 512
#define Ww 512
#define Bb 2
#define PLANE (Hh * Ww)

__device__ __forceinline__ void load_plane(const float* __restrict__ x, int base,
                                           int hm, int h0, int hp,
                                           int wm, int w0, int wp,
                                           float* p, float* cm) {
    const float* r0 = x + base + hm * Ww;
    const float* r1 = x + base + h0 * Ww;
    const float* r2 = x + base + hp * Ww;
    p[0] = __ldg(r0 + wm); p[1] = __ldg(r0 + w0); p[2] = __ldg(r0 + wp);
    p[3] = __ldg(r1 + wm); p[4] = __ldg(r1 + w0); p[5] = __ldg(r1 + wp);
    p[6] = __ldg(r2 + wm); p[7] = __ldg(r2 + w0); p[8] = __ldg(r2 + wp);
    // Per-column maxima, cached for the 3 d-iterations that use this plane.
    cm[0] = fmaxf(p[0], fmaxf(p[3], p[6]));
    cm[1] = fmaxf(p[1], fmaxf(p[4], p[7]));
    cm[2] = fmaxf(p[2], fmaxf(p[5], p[8]));
}

__global__ void __launch_bounds__(128, 7)
conv_quad_interp3d_kernel(const float* __restrict__ x, float* __restrict__ out) {
    const int w = blockIdx.x * 32 + threadIdx.x;
    const int h = blockIdx.y * 4 + threadIdx.y;
    const int b = blockIdx.z;

    const int wm = max(w - 1, 0), wp = min(w + 1, Ww - 1);
    const int hm = max(h - 1, 0), hp = min(h + 1, Hh - 1);
    const int xbase = b * Dd * PLANE;

    // Rolling window: P0 = plane d-1, P1 = d, P2 = d+1 (replicate-clamped),
    // with per-plane column maxima cm0/cm1/cm2.
    float P0[9], P1[9], P2[9];
    float cm0[3], cm1[3], cm2[3];
    load_plane(x, xbase + 0 * PLANE, hm, h, hp, wm, w, wp, P1, cm1);
#pragma unroll
    for (int i = 0; i < 9; i++) P0[i] = P1[i];
#pragma unroll
    for (int i = 0; i < 3; i++) cm0[i] = cm1[i];
    load_plane(x, xbase + 1 * PLANE, hm, h, hp, wm, w, wp, P2, cm2);

    const int hw = h * Ww + w;
    float* coordsD = out + (b * 3 + 0) * Dd * PLANE;
    float* coordsW = out + (b * 3 + 1) * Dd * PLANE;
    float* coordsH = out + (b * 3 + 2) * Dd * PLANE;
    float* ymax    = out + (Bb * 3) * Dd * PLANE + b * Dd * PLANE;

#pragma unroll
    for (int d = 0; d < Dd; d++) {
        const float c = P1[4];

        // Gradients (central diff / 2, replicate pad); b = [gx(W), gy(H), gs(D)]
        const float gx = 0.5f * (P1[5] - P1[3]);
        const float gy = 0.5f * (P1[7] - P1[1]);
        const float gs = 0.5f * (P2[4] - P0[4]);

        // Hessian (cross terms * 0.25 per reference)
        const float axx = P1[3] + P1[5] - 2.0f * c;
        const float ayy = P1[1] + P1[7] - 2.0f * c;
        const float ass = P0[4] + P2[4] - 2.0f * c;
        const float axy = 0.25f * (P1[0] + P1[8] - P1[6] - P1[2]);
        const float ays = 0.25f * (P0[1] + P2[7] - P2[1] - P0[7]);
        const float axs = 0.25f * (P0[3] + P2[5] - P2[3] - P0[5]);

        // Separable NMS: max over 27 = max over 9 cached column maxima.
        float m = fmaxf(cm0[0], fmaxf(cm0[1], cm0[2]));
        m = fmaxf(m, fmaxf(cm1[0], fmaxf(cm1[1], cm1[2])));
        m = fmaxf(m, fmaxf(cm2[0], fmaxf(cm2[1], cm2[2])));
        const bool nms = (c == m);

        // Symmetric 3x3 solve via adjugate (Cramer)
        const float c00 = ayy * ass - ays * ays;
        const float c01 = axs * ays - axy * ass;
        const float c02 = axy * ays - axs * ayy;
        const float det = axx * c00 + axy * c01 + axs * c02;
        const bool keep = nms && (det != 0.0f);

        float rx = 0.0f, ry = 0.0f, rs = 0.0f;
        if (keep) {
            const float inv = 1.0f / det;
            const float c11 = axx * ass - axs * axs;
            const float c12 = axy * axs - axx * ays;
            const float c22 = axx * ayy - axy * axy;
            rx = -(c00 * gx + c01 * gy + c02 * gs) * inv;
            ry = -(c01 * gx + c11 * gy + c12 * gs) * inv;
            rs = -(c02 * gx + c12 * gy + c22 * gs) * inv;
            const float big = fmaxf(fabsf(rx), fmaxf(fabsf(ry), fabsf(rs)));
            if (big > 0.7f) { rx = 0.0f; ry = 0.0f; rs = 0.0f; }
        }

        const float dyv = 0.5f * (gx * rx + gy * ry + gs * rs);
        const float y = c + dyv + (keep ? 10.0f : 0.0f);

        // coords channels: grid(d, w, h) + flipped refinement (s, y, x)
        const int dhw = d * PLANE + hw;
        coordsD[dhw] = (float)d + rs;
        coordsW[dhw] = (float)w + ry;
        coordsH[dhw] = (float)h + rx;
        ymax[dhw]    = y;

        if (d < Dd - 1) {
#pragma unroll
            for (int i = 0; i < 9; i++) { P0[i] = P1[i]; P1[i] = P2[i]; }
#pragma unroll
            for (int i = 0; i < 3; i++) { cm0[i] = cm1[i]; cm1[i] = cm2[i]; }
            const int dn = min(d + 2, Dd - 1);
            load_plane(x, xbase + dn * PLANE, hm, h, hp, wm, w, wp, P2, cm2);
        }
    }
}

extern "C" void kernel_launch(void* const* d_in, const int* in_sizes, int n_in,
                              void* d_out, int out_size) {
    const float* x = (const float*)d_in[0];
    float* out = (float*)d_out;
    dim3 block(32, 4, 1);
    dim3 grid(Ww / 32, Hh / 4, Bb);  // (16, 128, 2)
    conv_quad_interp3d_kernel<<<grid, block>>>(x, out);
}